// round 6
// baseline (speedup 1.0000x reference)
#include <cuda_runtime.h>

#define NTOT  22743
#define NB    64
#define CAP   8192
#define NEGF  -1e9f

#define BLKA  256
#define RPT   8
#define CHUNK (BLKA * RPT)     // 2048
#define CPB   12               // chunks per image: 12*2048 >= 22743

typedef unsigned long long ull;

// per-image compacted candidate keys: (score_bits << 32) | ~anchor_idx
__device__ ull g_cand[(size_t)NB * CAP];
__device__ int g_cnt[NB];             // zeroed at init; kernel B resets after use
__device__ int g_hist[NB * 1024];     // per-image score-bucket histogram

// anchors in pixels: level*3 + a  (w, h)
__constant__ float c_aw[9] = {116.f, 156.f, 373.f,  30.f, 62.f, 59.f,  10.f, 16.f, 33.f};
__constant__ float c_ah[9] = { 90.f, 198.f, 326.f,  61.f, 45.f, 119.f, 13.f, 30.f, 23.f};

__device__ __forceinline__ const float* rec_ptrf(const float* p0, const float* p1,
                                                 const float* p2, int b, int n) {
    if (n < 1083)  return p0 + ((size_t)b * 1083 + n) * 26;
    if (n < 5415)  return p1 + ((size_t)b * 4332 + (n - 1083)) * 26;
    return p2 + ((size_t)b * 17328 + (n - 5415)) * 26;
}

__device__ __forceinline__ int bucket_of(unsigned score_bits) {
    return min(max((int)(score_bits >> 15) - 0x7C00, 0), 1023);
}

// ---------------------------------------------------------------------------
// Kernel A: 2-D grid (chunk, image) so b is block-uniform. Phase 1: batched
// gate loads (MLP=8) -> smem queue. Phase 2: 8-lane-cooperative softmax
// (one float4 per lane from the record's aligned 128B window).
// ---------------------------------------------------------------------------
__global__ __launch_bounds__(BLKA) void score_kernel(
    const float* __restrict__ p0, const float* __restrict__ p1,
    const float* __restrict__ p2) {

    __shared__ int q[CHUNK];
    __shared__ int qn;

    int tid = threadIdx.x;
    int lane = tid & 31;
    int wid = tid >> 5;
    int b = blockIdx.y;
    int n0 = blockIdx.x * CHUNK;

    if (tid == 0) qn = 0;
    __syncthreads();

    // ---- phase 1: 8 independent gate loads per thread ----
    float2 gate[RPT];
    int nn[RPT];
#pragma unroll
    for (int r = 0; r < RPT; r++) {
        int n = n0 + r * BLKA + tid;
        nn[r] = n;
        if (n < NTOT) {
            gate[r] = __ldg((const float2*)(rec_ptrf(p0, p1, p2, b, n) + 4));
        } else {
            gate[r] = make_float2(NEGF, NEGF);
        }
    }

    // obj >= 0.6 <=> logit >= ln(1.5); loc >= 0.5 <=> logit >= 0
#pragma unroll
    for (int r = 0; r < RPT; r++) {
        bool pass = (nn[r] < NTOT) &&
                    (gate[r].x >= 0.40546510810816444f) && (gate[r].y >= 0.0f);
        unsigned m = __ballot_sync(0xFFFFFFFFu, pass);
        if (pass) {
            int leader = __ffs(m) - 1;
            int rank = __popc(m & ((1u << lane) - 1u));
            int bp = 0;
            if (lane == leader) bp = atomicAdd(&qn, __popc(m));
            bp = __shfl_sync(m, bp, leader);
            q[bp + rank] = nn[r];
        }
    }
    __syncthreads();

    int ne = qn;
    int g = lane >> 3;          // group 0..3 within warp
    int sub = lane & 7;         // lane within 8-lane group

    // ---- phase 2: each 8-lane group processes one queued record ----
    for (int base2 = wid * 4; base2 < ne; base2 += 32) {
        int slot = base2 + g;
        bool gact = slot < ne;
        int n = q[gact ? slot : 0];
        const float* rec = rec_ptrf(p0, p1, p2, b, n);
        size_t ra = (size_t)rec;
        int off = (int)((ra >> 2) & 3);                  // 0 or 2
        const float4* ab = (const float4*)(ra & ~(size_t)15);

        float4 f = make_float4(0.f, 0.f, 0.f, 0.f);
        if (sub < 7) f = __ldg(ab + sub);                // aligned floats [4sub,4sub+4)
        float v[4] = {f.x, f.y, f.z, f.w};

        // partial max over this lane's class logits (record float j in [6,25])
        float mx = -1e30f;
#pragma unroll
        for (int k = 0; k < 4; k++) {
            int j = sub * 4 + k - off;
            if (j >= 6 && j <= 25) mx = fmaxf(mx, v[k]);
        }
#pragma unroll
        for (int d = 1; d < 8; d <<= 1)
            mx = fmaxf(mx, __shfl_xor_sync(0xFFFFFFFFu, mx, d));

        float es = 0.f;
#pragma unroll
        for (int k = 0; k < 4; k++) {
            int j = sub * 4 + k - off;
            if (j >= 6 && j <= 25) es += __expf(v[k] - mx);
        }
#pragma unroll
        for (int d = 1; d < 8; d <<= 1)
            es += __shfl_xor_sync(0xFFFFFFFFu, es, d);

        // lane sub==1 holds obj (j=4 -> k=off) and loc (j=5 -> k=off+1)
        float sc = NEGF;
        bool push = false;
        if (sub == 1 && gact) {
            float obj = __fdividef(1.f, 1.f + __expf(-v[off]));
            float conf = __fdividef(obj, es);            // obj * max(softmax)
            if (conf >= 0.05f) {
                float loc = __fdividef(1.f, 1.f + __expf(-v[off + 1]));
                sc = sqrtf(conf) * sqrtf(loc);
            }
            push = sc > 0.f;
        }

        unsigned m = __ballot_sync(0xFFFFFFFFu, push);
        if (push) {
            int leader = __ffs(m) - 1;
            int rank = __popc(m & ((1u << lane) - 1u));
            int bp = 0;
            if (lane == leader) bp = atomicAdd(&g_cnt[b], __popc(m));
            bp = __shfl_sync(m, bp, leader);
            int p = bp + rank;
            unsigned sb = __float_as_uint(sc);
            if (p < CAP)
                g_cand[(size_t)b * CAP + p] =
                    ((ull)sb << 32) | (unsigned)(~(unsigned)n);
            atomicAdd(&g_hist[b * 1024 + bucket_of(sb)], 1);
        }
    }
}

// ---------------------------------------------------------------------------
// Kernel B: one block per image. Radix-select (precomputed histogram +
// warp-shuffle suffix scan) -> low-barrier bitonic sort -> vectorized decode
// -> per-class parallel soft-NMS (one warp per class) -> parallel top-8 out.
// ---------------------------------------------------------------------------
__global__ __launch_bounds__(1024) void select_nms_kernel(
    const float* __restrict__ p0, const float* __restrict__ p1,
    const float* __restrict__ p2, float* __restrict__ out) {

    __shared__ ull    keys2[2048];
    __shared__ int    suf[1024];
    __shared__ int    wsum[32];
    __shared__ int    wsuf[32];
    __shared__ float4 cbox[256];
    __shared__ float  cval[256];
    __shared__ float  carea[256];
    __shared__ int    ccls[256];
    __shared__ unsigned char kept[256];
    __shared__ unsigned char clist[20][64];
    __shared__ unsigned kmask[8];
    __shared__ int s_T, s_col, s_cnt;

    int tid = threadIdx.x;
    int lane = tid & 31;
    int w = tid >> 5;
    int b = blockIdx.x;

    if (tid == 0) {
        s_cnt = min(g_cnt[b], CAP);
        g_cnt[b] = 0;                        // reset for next call (graph-safe)
        s_col = 0;
        s_T = 0;
    }
    int hv = g_hist[b * 1024 + tid];         // histogram built by kernel A
    g_hist[b * 1024 + tid] = 0;              // reset for next call
    if (tid < 256) kept[tid] = 0;
    __syncthreads();

    int cnt = s_cnt;
    const ull* cand = g_cand + (size_t)b * CAP;

    // ---- suffix scan via warp shuffles ----
    int v = hv;
#pragma unroll
    for (int s = 1; s < 32; s <<= 1) {
        int t2 = __shfl_down_sync(0xFFFFFFFFu, v, s);
        if (lane + s < 32) v += t2;
    }
    if (lane == 0) wsum[w] = v;              // chunk total (suffix at lane 0)
    __syncthreads();
    if (w == 0) {
        int x = wsum[lane];
        int tot0 = x;
#pragma unroll
        for (int s = 1; s < 32; s <<= 1) {
            int t2 = __shfl_down_sync(0xFFFFFFFFu, x, s);
            if (lane + s < 32) x += t2;
        }
        wsuf[lane] = x - tot0;               // exclusive suffix of later warps
    }
    __syncthreads();
    int sufv = v + wsuf[w];
    suf[tid] = sufv;
    __syncthreads();
    // threshold bucket T: largest i with suffix[i] >= 256 (0 if total < 256)
    if (sufv >= 256 && (tid == 1023 || suf[tid + 1] < 256)) s_T = tid;
    __syncthreads();
    int T = s_T;

    // ---- compact entries in buckets >= T ----
    for (int i = tid; i < cnt; i += 1024) {
        ull k = __ldg(cand + i);
        int bk = bucket_of((unsigned)(k >> 32));
        if (bk >= T) {
            int p = atomicAdd(&s_col, 1);
            if (p < 2048) keys2[p] = k;
        }
    }
    __syncthreads();
    int col = min(s_col, 2048);
    int n2 = 256;
    while (n2 < col) n2 <<= 1;
    for (int i = col + tid; i < n2; i += 1024) keys2[i] = 0ULL;
    __syncthreads();

    // ---- bitonic sort (descending); j<32 passes are warp-local ----
    for (int k = 2; k <= n2; k <<= 1) {
        for (int j = k >> 1; j > 0; j >>= 1) {
            for (int i = tid; i < n2; i += 1024) {
                int l = i ^ j;
                if (l > i) {
                    ull a = keys2[i], c2 = keys2[l];
                    bool desc = ((i & k) == 0);
                    if ((a < c2) == desc) { keys2[i] = c2; keys2[l] = a; }
                }
            }
            if (j >= 32) __syncthreads(); else __syncwarp();
        }
    }
    __syncthreads();

    // ---- decode top-256 candidates (vectorized loads) ----
    if (tid < 256) {
        ull kk = keys2[tid];
        float4 bx = make_float4(0.f, 0.f, 0.f, 0.f);
        int cls = 255;               // never matches a class warp (0..19)
        float val = NEGF;
        float area = 0.f;
        if (kk != 0ULL) {
            unsigned n = ~(unsigned)(kk & 0xFFFFFFFFull);
            val = __uint_as_float((unsigned)(kk >> 32));
            int lvl, r, GG, G; float strd; const float* base;
            if (n < 1083u) {
                lvl = 0; r = (int)n;        GG = 361;  G = 19; strd = 32.f;
                base = p0 + (size_t)b * 1083 * 26;
            } else if (n < 5415u) {
                lvl = 1; r = (int)n - 1083; GG = 1444; G = 38; strd = 16.f;
                base = p1 + (size_t)b * 4332 * 26;
            } else {
                lvl = 2; r = (int)n - 5415; GG = 5776; G = 76; strd = 8.f;
                base = p2 + (size_t)b * 17328 * 26;
            }
            int a = r / GG; int cell = r - a * GG;
            int gy = cell / G; int gx = cell - gy * G;
            const float* rec = base + (size_t)r * 26;
            float tx, ty, tw, th, cl[20];
            if (((size_t)rec & 15) == 0) {
                float4 q0 = __ldg((const float4*)rec);            // f0..3
                float4 q1 = __ldg((const float4*)(rec + 4));      // f4..7
                float4 q2 = __ldg((const float4*)(rec + 8));
                float4 q3 = __ldg((const float4*)(rec + 12));
                float4 q4 = __ldg((const float4*)(rec + 16));
                float4 q5 = __ldg((const float4*)(rec + 20));     // f20..23
                float2 q6 = __ldg((const float2*)(rec + 24));
                tx = q0.x; ty = q0.y; tw = q0.z; th = q0.w;
                cl[0] = q1.z;  cl[1] = q1.w;
                cl[2] = q2.x;  cl[3] = q2.y;  cl[4] = q2.z;  cl[5] = q2.w;
                cl[6] = q3.x;  cl[7] = q3.y;  cl[8] = q3.z;  cl[9] = q3.w;
                cl[10] = q4.x; cl[11] = q4.y; cl[12] = q4.z; cl[13] = q4.w;
                cl[14] = q5.x; cl[15] = q5.y; cl[16] = q5.z; cl[17] = q5.w;
                cl[18] = q6.x; cl[19] = q6.y;
            } else {
                float2 q0 = __ldg((const float2*)rec);            // f0,f1
                float4 q1 = __ldg((const float4*)(rec + 2));      // f2..5
                float4 q2 = __ldg((const float4*)(rec + 6));      // f6..9
                float4 q3 = __ldg((const float4*)(rec + 10));
                float4 q4 = __ldg((const float4*)(rec + 14));
                float4 q5 = __ldg((const float4*)(rec + 18));     // f18..21
                float4 q6 = __ldg((const float4*)(rec + 22));     // f22..25
                tx = q0.x; ty = q0.y; tw = q1.x; th = q1.y;
                cl[0] = q2.x;  cl[1] = q2.y;  cl[2] = q2.z;  cl[3] = q2.w;
                cl[4] = q3.x;  cl[5] = q3.y;  cl[6] = q3.z;  cl[7] = q3.w;
                cl[8] = q4.x;  cl[9] = q4.y;  cl[10] = q4.z; cl[11] = q4.w;
                cl[12] = q5.x; cl[13] = q5.y; cl[14] = q5.z; cl[15] = q5.w;
                cl[16] = q6.x; cl[17] = q6.y; cl[18] = q6.z; cl[19] = q6.w;
            }
            float m = cl[0]; int ci = 0;
#pragma unroll
            for (int c = 1; c < 20; c++)
                if (cl[c] > m) { m = cl[c]; ci = c; }
            float sx = __fdividef(1.f, 1.f + __expf(-tx));
            float sy = __fdividef(1.f, 1.f + __expf(-ty));
            float cx = (sx + (float)gx) * strd;
            float cy = (sy + (float)gy) * strd;
            float ww2 = __expf(tw) * c_aw[lvl * 3 + a];
            float hh = __expf(th) * c_ah[lvl * 3 + a];
            float x1 = fminf(fmaxf(cx - 0.5f * ww2, 0.f), 608.f);
            float y1 = fminf(fmaxf(cy - 0.5f * hh, 0.f), 608.f);
            float x2 = fminf(fmaxf(cx + 0.5f * ww2, 0.f), 608.f);
            float y2 = fminf(fmaxf(cy + 0.5f * hh, 0.f), 608.f);
            bx = make_float4(x1, y1, x2, y2);
            area = (x2 - x1 + 1.f) * (y2 - y1 + 1.f);
            cls = ci;
        }
        cbox[tid] = bx;
        cval[tid] = val;
        carea[tid] = area;
        ccls[tid] = cls;
    }
    __syncthreads();

    // ---- per-class soft-NMS: warp w handles class w (classes decouple) ----
    if (w < 20) {
        int c = w;
        int cntc = 0;
        for (int g = 0; g < 8; g++) {
            int ci2 = g * 32 + lane;
            bool take = (ccls[ci2] == c);
            unsigned mm = __ballot_sync(0xFFFFFFFFu, take);
            if (take) {
                int pos = cntc + __popc(mm & ((1u << lane) - 1u));
                if (pos < 64) clist[c][pos] = (unsigned char)ci2;
            }
            cntc += __popc(mm);
        }
        if (cntc > 64) cntc = 64;
        __syncwarp();

        int cand0 = (lane < cntc) ? (int)clist[c][lane] : -1;
        int cand1 = (lane + 32 < cntc) ? (int)clist[c][lane + 32] : -1;
        float s0f = (cand0 >= 0) ? cval[cand0] : NEGF;
        float s1f = (cand1 >= 0) ? cval[cand1] : NEGF;
        float4 b0 = (cand0 >= 0) ? cbox[cand0] : make_float4(0.f, 0.f, 0.f, 0.f);
        float4 b1 = (cand1 >= 0) ? cbox[cand1] : make_float4(0.f, 0.f, 0.f, 0.f);
        float a0 = (cand0 >= 0) ? carea[cand0] : 0.f;
        float a1 = (cand1 >= 0) ? carea[cand1] : 0.f;

        while (true) {
            float sm; int im;
            if (s1f > s0f) { sm = s1f; im = cand1; }
            else           { sm = s0f; im = cand0; }   // tie -> lower cand idx
            unsigned kb = (sm > 0.f) ? __float_as_uint(sm) : 0u;
            unsigned gmax = __reduce_max_sync(0xFFFFFFFFu, kb);
            if (gmax < 0x3DCCCCCDu) break;             // 0.1f as bits
            int mi = (kb == gmax) ? im : 0x7FFFFFFF;
            int j = __reduce_min_sync(0xFFFFFFFFu, mi);
            if (lane == 0) kept[j] = 1;
            float4 bj = cbox[j];
            float aj = carea[j];
            if (cand0 >= 0) {
                if (cand0 == j) s0f = NEGF;
                else {
                    float ix1 = fmaxf(bj.x, b0.x), iy1 = fmaxf(bj.y, b0.y);
                    float ix2 = fminf(bj.z, b0.z), iy2 = fminf(bj.w, b0.w);
                    float inter = fmaxf(ix2 - ix1 + 1.f, 0.f) *
                                  fmaxf(iy2 - iy1 + 1.f, 0.f);
                    if (inter > 0.f) {   // exp(0)=1 exactly -> skip is exact
                        float iou = __fdividef(inter, aj + a0 - inter + 1e-16f);
                        s0f *= __expf(-2.f * iou * iou);
                    }
                }
            }
            if (cand1 >= 0) {
                if (cand1 == j) s1f = NEGF;
                else {
                    float ix1 = fmaxf(bj.x, b1.x), iy1 = fmaxf(bj.y, b1.y);
                    float ix2 = fminf(bj.z, b1.z), iy2 = fminf(bj.w, b1.w);
                    float inter = fmaxf(ix2 - ix1 + 1.f, 0.f) *
                                  fmaxf(iy2 - iy1 + 1.f, 0.f);
                    if (inter > 0.f) {
                        float iou = __fdividef(inter, aj + a1 - inter + 1e-16f);
                        s1f *= __expf(-2.f * iou * iou);
                    }
                }
            }
        }
    }
    __syncthreads();

    // ---- parallel output: rank kept candidates, write first 8 ----
    if (tid < 256) {
        unsigned bal = __ballot_sync(0xFFFFFFFFu, kept[tid] != 0);
        if (lane == 0) kmask[tid >> 5] = bal;
    }
    __syncthreads();
    if (tid < 256 && kept[tid]) {
        int pre = 0;
#pragma unroll
        for (int ww = 0; ww < 8; ww++)
            if (ww < (tid >> 5)) pre += __popc(kmask[ww]);
        pre += __popc(kmask[tid >> 5] & ((1u << lane) - 1u));
        if (pre < 8) {
            float* o = out + (size_t)b * 48 + pre * 6;
            float4 bb = cbox[tid];
            o[0] = bb.x; o[1] = bb.y; o[2] = bb.z; o[3] = bb.w;
            o[4] = cval[tid];
            o[5] = (float)ccls[tid];
        }
    }
    if (tid >= 256 && tid < 264) {
        int K = 0;
#pragma unroll
        for (int ww = 0; ww < 8; ww++) K += __popc(kmask[ww]);
        int slot = tid - 256;
        if (slot >= K) {
            float* o = out + (size_t)b * 48 + slot * 6;
#pragma unroll
            for (int q2 = 0; q2 < 6; q2++) o[q2] = 0.f;
        }
    }
}

extern "C" void kernel_launch(void* const* d_in, const int* in_sizes, int n_in,
                              void* d_out, int out_size) {
    const float* p0 = (const float*)d_in[0];
    const float* p1 = (const float*)d_in[1];
    const float* p2 = (const float*)d_in[2];
    float* out = (float*)d_out;

    dim3 gridA(CPB, NB);
    score_kernel<<<gridA, BLKA>>>(p0, p1, p2);
    select_nms_kernel<<<NB, 1024>>>(p0, p1, p2, out);
}

// round 8
// speedup vs baseline: 1.2016x; 1.2016x over previous
#include <cuda_runtime.h>

#define NTOT  22743
#define NB    64
#define CAP   8192
#define NEGF  -1e9f

#define BLKA  256
#define RPT   8
#define CHUNK (BLKA * RPT)     // 2048
#define CPB   12               // 12*2048 >= 22743

typedef unsigned long long ull;

// per-image compacted candidate keys: (score_bits << 32) | ~anchor_idx
__device__ ull g_cand[(size_t)NB * CAP];
__device__ int g_cnt[NB];             // zeroed at init; kernel B resets after use
__device__ int g_hist[NB * 1024];     // per-image score-bucket histogram

// anchors in pixels: level*3 + a  (w, h)
__constant__ float c_aw[9] = {116.f, 156.f, 373.f,  30.f, 62.f, 59.f,  10.f, 16.f, 33.f};
__constant__ float c_ah[9] = { 90.f, 198.f, 326.f,  61.f, 45.f, 119.f, 13.f, 30.f, 23.f};

__device__ __forceinline__ const float* rec_ptrf(const float* p0, const float* p1,
                                                 const float* p2, int b, int n) {
    if (n < 1083)  return p0 + ((size_t)b * 1083 + n) * 26;
    if (n < 5415)  return p1 + ((size_t)b * 4332 + (n - 1083)) * 26;
    return p2 + ((size_t)b * 17328 + (n - 5415)) * 26;
}

__device__ __forceinline__ int bucket_of(unsigned sb) {
    return min(max((int)(sb >> 15) - 0x7C00, 0), 1023);
}

// ---------------------------------------------------------------------------
// Kernel A (R3 structure, 2-D grid): batched gate loads (MLP=8) -> smem queue
// -> dense per-thread softmax. Gate on raw logits (no transcendentals).
// ---------------------------------------------------------------------------
__global__ __launch_bounds__(BLKA) void score_kernel(
    const float* __restrict__ p0, const float* __restrict__ p1,
    const float* __restrict__ p2) {

    __shared__ int q[CHUNK];
    __shared__ int qn;

    int tid = threadIdx.x;
    int lane = tid & 31;
    int b = blockIdx.y;
    int n0 = blockIdx.x * CHUNK;

    if (tid == 0) qn = 0;
    __syncthreads();

    // ---- phase 1: 8 independent gate loads per thread ----
    float2 gate[RPT];
    int nn[RPT];
#pragma unroll
    for (int r = 0; r < RPT; r++) {
        int n = n0 + r * BLKA + tid;
        nn[r] = n;
        if (n < NTOT)
            gate[r] = __ldg((const float2*)(rec_ptrf(p0, p1, p2, b, n) + 4));
        else
            gate[r] = make_float2(NEGF, NEGF);
    }

    // obj >= 0.6 <=> logit >= ln(1.5); loc >= 0.5 <=> logit >= 0
#pragma unroll
    for (int r = 0; r < RPT; r++) {
        bool pass = (nn[r] < NTOT) &&
                    (gate[r].x >= 0.40546510810816444f) && (gate[r].y >= 0.0f);
        unsigned m = __ballot_sync(0xFFFFFFFFu, pass);
        if (pass) {
            int leader = __ffs(m) - 1;
            int rank = __popc(m & ((1u << lane) - 1u));
            int bp = 0;
            if (lane == leader) bp = atomicAdd(&qn, __popc(m));
            bp = __shfl_sync(m, bp, leader);
            q[bp + rank] = nn[r];
        }
    }
    __syncthreads();

    int ne = qn;

    // ---- phase 2: dense per-thread softmax over queued records ----
    for (int i0 = 0; i0 < ne; i0 += BLKA) {
        int i = i0 + tid;
        bool act = i < ne;
        int n = act ? q[i] : 0;
        float sc = NEGF;
        if (act) {
            const float2* rec2 = (const float2*)rec_ptrf(p0, p1, p2, b, n);
            float2 g = __ldg(rec2 + 2);
            float2 l[10];
#pragma unroll
            for (int k = 0; k < 10; k++) l[k] = __ldg(rec2 + 3 + k);  // f6..f25
            float mx = fmaxf(l[0].x, l[0].y);
#pragma unroll
            for (int k = 1; k < 10; k++) mx = fmaxf(mx, fmaxf(l[k].x, l[k].y));
            float ssum = 0.f;
#pragma unroll
            for (int k = 0; k < 10; k++)
                ssum += __expf(l[k].x - mx) + __expf(l[k].y - mx);
            float obj = __fdividef(1.f, 1.f + __expf(-g.x));
            float conf = __fdividef(obj, ssum);             // obj * max(softmax)
            if (conf >= 0.05f) {
                float loc = __fdividef(1.f, 1.f + __expf(-g.y));
                sc = sqrtf(conf) * sqrtf(loc);
            }
        }
        bool push = act && (sc > 0.f);
        unsigned m = __ballot_sync(0xFFFFFFFFu, push);
        if (push) {
            int leader = __ffs(m) - 1;
            int rank = __popc(m & ((1u << lane) - 1u));
            int bp = 0;
            if (lane == leader) bp = atomicAdd(&g_cnt[b], __popc(m));
            bp = __shfl_sync(m, bp, leader);
            int p = bp + rank;
            unsigned sb = __float_as_uint(sc);
            if (p < CAP)
                g_cand[(size_t)b * CAP + p] =
                    ((ull)sb << 32) | (unsigned)(~(unsigned)n);
            atomicAdd(&g_hist[b * 1024 + bucket_of(sb)], 1);
        }
    }
}

// block-wide inclusive suffix scan over 1024 values; fills suf[], returns suffix@tid
__device__ __forceinline__ int suffix_scan_1024(int v, int tid, int lane, int w,
                                                int* suf, int* wsum, int* wsuf) {
#pragma unroll
    for (int s = 1; s < 32; s <<= 1) {
        int t2 = __shfl_down_sync(0xFFFFFFFFu, v, s);
        if (lane + s < 32) v += t2;
    }
    if (lane == 0) wsum[w] = v;
    __syncthreads();
    if (w == 0) {
        int x = wsum[lane];
        int tot0 = x;
#pragma unroll
        for (int s = 1; s < 32; s <<= 1) {
            int t2 = __shfl_down_sync(0xFFFFFFFFu, x, s);
            if (lane + s < 32) x += t2;
        }
        wsuf[lane] = x - tot0;          // suffix of later warps (exclusive)
    }
    __syncthreads();
    int sv = v + wsuf[w];
    suf[tid] = sv;
    __syncthreads();
    return sv;
}

// ---------------------------------------------------------------------------
// Kernel B: one block per image. SORT-FREE exact top-256 via 3-level radix
// select -> decode (unsorted) -> per-class soft-NMS with lexicographic
// (decayed-score, orig-key) argmax -> key-ranked top-8 output.
// ---------------------------------------------------------------------------
__global__ __launch_bounds__(1024) void select_nms_kernel(
    const float* __restrict__ p0, const float* __restrict__ p1,
    const float* __restrict__ p2, float* __restrict__ out) {

    __shared__ ull    keyT[2048];     // bucket == T entries
    __shared__ ull    keyU[512];      // sub-bucket == T2 entries
    __shared__ ull    acc[256];       // accepted top-256 set (unsorted)
    __shared__ int    hist2[1024];
    __shared__ int    suf[1024];
    __shared__ int    wsum[32], wsuf[32];
    __shared__ float4 cbox[256];
    __shared__ float  cval[256];
    __shared__ float  carea[256];
    __shared__ int    ccls[256];
    __shared__ unsigned cn[256];      // ~anchor_idx (key low 32)
    __shared__ unsigned char kept[256];
    __shared__ unsigned char clist[20][64];
    __shared__ unsigned kmask[8];
    __shared__ int sT, sT2, s_na, s_ntc, s_nu, s_cnt;

    int tid = threadIdx.x;
    int lane = tid & 31;
    int w = tid >> 5;
    int b = blockIdx.x;

    if (tid == 0) {
        s_cnt = min(g_cnt[b], CAP);
        g_cnt[b] = 0;                         // reset (graph-safe)
        s_na = 0; s_ntc = 0; s_nu = 0; sT = 0; sT2 = 0;
    }
    int hv = g_hist[b * 1024 + tid];
    g_hist[b * 1024 + tid] = 0;
    hist2[tid] = 0;
    if (tid < 256) kept[tid] = 0;
    __syncthreads();

    int cnt = s_cnt;
    const ull* cand = g_cand + (size_t)b * CAP;

    // ---- level-1: suffix scan over 1024 score buckets ----
    int sv = suffix_scan_1024(hv, tid, lane, w, suf, wsum, wsuf);
    int total = suf[0];
    bool simple = (total <= 256);
    if (!simple) {
        // T = largest bucket with suffix >= 256
        if (sv >= 256 && (tid == 1023 || suf[tid + 1] < 256)) sT = tid;
    }
    __syncthreads();
    int T = sT;
    int nh = 0, need = 0;
    if (!simple) {
        nh = (T < 1023) ? suf[T + 1] : 0;     // definite members (buckets > T)
        need = 256 - nh;                      // needed from bucket T (>=1)
    }

    // ---- compact: definite members -> acc; bucket-T entries -> keyT ----
    for (int i = tid; i < cnt; i += 1024) {
        ull k = __ldg(cand + i);
        int bk = bucket_of((unsigned)(k >> 32));
        if (simple || bk > T) {
            int p = atomicAdd(&s_na, 1);
            acc[p] = k;                       // p < 256 guaranteed
        } else if (bk == T) {
            int p = atomicAdd(&s_ntc, 1);
            if (p < 2048) keyT[p] = k;
        }
    }
    __syncthreads();

    if (!simple) {
        int nt = min(s_ntc, 2048);
        if (nt == need) {
            for (int i = tid; i < nt; i += 1024) {
                int p = atomicAdd(&s_na, 1);
                acc[p] = keyT[i];
            }
            __syncthreads();
        } else {
            // ---- level-2: refine bucket T by next 10 score bits ----
            for (int i = tid; i < nt; i += 1024)
                atomicAdd(&hist2[(int)((keyT[i] >> 37) & 0x3FF)], 1);
            __syncthreads();
            int sv2 = suffix_scan_1024(hist2[tid], tid, lane, w, suf, wsum, wsuf);
            if (sv2 >= need && (tid == 1023 || suf[tid + 1] < need)) sT2 = tid;
            __syncthreads();
            int T2 = sT2;
            int nh2 = (T2 < 1023) ? suf[T2 + 1] : 0;
            int need2 = need - nh2;           // >= 1
            for (int i = tid; i < nt; i += 1024) {
                ull k = keyT[i];
                int sb2 = (int)((k >> 37) & 0x3FF);
                if (sb2 > T2) {
                    int p = atomicAdd(&s_na, 1);
                    acc[p] = k;
                } else if (sb2 == T2) {
                    int p = atomicAdd(&s_nu, 1);
                    if (p < 512) keyU[p] = k;
                }
            }
            __syncthreads();
            // ---- level-3: exact rank among tiny collision set (full key) ----
            int nu = min(s_nu, 512);
            for (int e = tid; e < nu; e += 1024) {
                ull ke = keyU[e];
                int rank = 0;
                for (int u = 0; u < nu; u++) rank += (keyU[u] > ke);
                if (rank < need2) {
                    int p = atomicAdd(&s_na, 1);
                    acc[p] = ke;
                }
            }
            __syncthreads();
        }
    }

    int na = s_na;                            // == min(total, 256)
    for (int i = na + tid; i < 256; i += 1024) acc[i] = 0ULL;
    __syncthreads();

    // ---- decode the 256-member set (unsorted; vectorized loads) ----
    if (tid < 256) {
        ull kk = acc[tid];
        float4 bx = make_float4(0.f, 0.f, 0.f, 0.f);
        int cls = 255;                // never matches a class warp (0..19)
        float val = NEGF;
        float area = 0.f;
        unsigned klo = 0;
        if (kk != 0ULL) {
            unsigned n = ~(unsigned)(kk & 0xFFFFFFFFull);
            klo = (unsigned)(kk & 0xFFFFFFFFull);
            val = __uint_as_float((unsigned)(kk >> 32));
            int lvl, r, GG, G; float strd; const float* base;
            if (n < 1083u) {
                lvl = 0; r = (int)n;        GG = 361;  G = 19; strd = 32.f;
                base = p0 + (size_t)b * 1083 * 26;
            } else if (n < 5415u) {
                lvl = 1; r = (int)n - 1083; GG = 1444; G = 38; strd = 16.f;
                base = p1 + (size_t)b * 4332 * 26;
            } else {
                lvl = 2; r = (int)n - 5415; GG = 5776; G = 76; strd = 8.f;
                base = p2 + (size_t)b * 17328 * 26;
            }
            int a = r / GG; int cell = r - a * GG;
            int gy = cell / G; int gx = cell - gy * G;
            const float* rec = base + (size_t)r * 26;
            float tx, ty, tw, th, cl[20];
            if (((size_t)rec & 15) == 0) {
                float4 q0 = __ldg((const float4*)rec);
                float4 q1 = __ldg((const float4*)(rec + 4));
                float4 q2 = __ldg((const float4*)(rec + 8));
                float4 q3 = __ldg((const float4*)(rec + 12));
                float4 q4 = __ldg((const float4*)(rec + 16));
                float4 q5 = __ldg((const float4*)(rec + 20));
                float2 q6 = __ldg((const float2*)(rec + 24));
                tx = q0.x; ty = q0.y; tw = q0.z; th = q0.w;
                cl[0] = q1.z;  cl[1] = q1.w;
                cl[2] = q2.x;  cl[3] = q2.y;  cl[4] = q2.z;  cl[5] = q2.w;
                cl[6] = q3.x;  cl[7] = q3.y;  cl[8] = q3.z;  cl[9] = q3.w;
                cl[10] = q4.x; cl[11] = q4.y; cl[12] = q4.z; cl[13] = q4.w;
                cl[14] = q5.x; cl[15] = q5.y; cl[16] = q5.z; cl[17] = q5.w;
                cl[18] = q6.x; cl[19] = q6.y;
            } else {
                float2 q0 = __ldg((const float2*)rec);
                float4 q1 = __ldg((const float4*)(rec + 2));
                float4 q2 = __ldg((const float4*)(rec + 6));
                float4 q3 = __ldg((const float4*)(rec + 10));
                float4 q4 = __ldg((const float4*)(rec + 14));
                float4 q5 = __ldg((const float4*)(rec + 18));
                float4 q6 = __ldg((const float4*)(rec + 22));
                tx = q0.x; ty = q0.y; tw = q1.x; th = q1.y;
                cl[0] = q2.x;  cl[1] = q2.y;  cl[2] = q2.z;  cl[3] = q2.w;
                cl[4] = q3.x;  cl[5] = q3.y;  cl[6] = q3.z;  cl[7] = q3.w;
                cl[8] = q4.x;  cl[9] = q4.y;  cl[10] = q4.z; cl[11] = q4.w;
                cl[12] = q5.x; cl[13] = q5.y; cl[14] = q5.z; cl[15] = q5.w;
                cl[16] = q6.x; cl[17] = q6.y; cl[18] = q6.z; cl[19] = q6.w;
            }
            float m = cl[0]; int ci = 0;
#pragma unroll
            for (int c = 1; c < 20; c++)
                if (cl[c] > m) { m = cl[c]; ci = c; }
            float sx = __fdividef(1.f, 1.f + __expf(-tx));
            float sy = __fdividef(1.f, 1.f + __expf(-ty));
            float cx = (sx + (float)gx) * strd;
            float cy = (sy + (float)gy) * strd;
            float ww2 = __expf(tw) * c_aw[lvl * 3 + a];
            float hh = __expf(th) * c_ah[lvl * 3 + a];
            float x1 = fminf(fmaxf(cx - 0.5f * ww2, 0.f), 608.f);
            float y1 = fminf(fmaxf(cy - 0.5f * hh, 0.f), 608.f);
            float x2 = fminf(fmaxf(cx + 0.5f * ww2, 0.f), 608.f);
            float y2 = fminf(fmaxf(cy + 0.5f * hh, 0.f), 608.f);
            bx = make_float4(x1, y1, x2, y2);
            area = (x2 - x1 + 1.f) * (y2 - y1 + 1.f);
            cls = ci;
        }
        cbox[tid] = bx;
        cval[tid] = val;
        carea[tid] = area;
        ccls[tid] = cls;
        cn[tid] = klo;
    }
    __syncthreads();

    // ---- per-class soft-NMS (one warp per class); selection = lexicographic
    //      max over (decayed score, original 64-bit key) == reference order ----
    if (w < 20) {
        int c = w;
        int cntc = 0;
        for (int g = 0; g < 8; g++) {
            int ci2 = g * 32 + lane;
            bool take = (ccls[ci2] == c);
            unsigned mm = __ballot_sync(0xFFFFFFFFu, take);
            if (take) {
                int pos = cntc + __popc(mm & ((1u << lane) - 1u));
                if (pos < 64) clist[c][pos] = (unsigned char)ci2;
            }
            cntc += __popc(mm);
        }
        if (cntc > 64) cntc = 64;
        __syncwarp();

        int c0 = (lane < cntc) ? (int)clist[c][lane] : -1;
        int c1 = (lane + 32 < cntc) ? (int)clist[c][lane + 32] : -1;
        float s0f = (c0 >= 0) ? cval[c0] : NEGF;
        float s1f = (c1 >= 0) ? cval[c1] : NEGF;
        unsigned kh0 = (c0 >= 0) ? __float_as_uint(cval[c0]) : 0u;
        unsigned kh1 = (c1 >= 0) ? __float_as_uint(cval[c1]) : 0u;
        unsigned kl0 = (c0 >= 0) ? cn[c0] : 0u;
        unsigned kl1 = (c1 >= 0) ? cn[c1] : 0u;
        float4 b0 = (c0 >= 0) ? cbox[c0] : make_float4(0.f, 0.f, 0.f, 0.f);
        float4 b1 = (c1 >= 0) ? cbox[c1] : make_float4(0.f, 0.f, 0.f, 0.f);
        float a0 = (c0 >= 0) ? carea[c0] : 0.f;
        float a1 = (c1 >= 0) ? carea[c1] : 0.f;

        while (true) {
            // lane-local best of two slots: (s, key) lexicographic
            bool p1;
            if (s1f != s0f) p1 = (s1f > s0f);
            else p1 = (kh1 > kh0) || (kh1 == kh0 && kl1 > kl0);
            float bs = p1 ? s1f : s0f;
            unsigned bh = p1 ? kh1 : kh0;
            unsigned bl = p1 ? kl1 : kl0;
            int bslot = p1 ? c1 : c0;

            unsigned sbits = (bs > 0.f) ? __float_as_uint(bs) : 0u;
            unsigned m1 = __reduce_max_sync(0xFFFFFFFFu, sbits);
            if (m1 < 0x3DCCCCCDu) break;               // 0.1f as bits
            bool q1 = (sbits == m1);
            unsigned m2 = __reduce_max_sync(0xFFFFFFFFu, q1 ? bh : 0u);
            bool q2 = q1 && (bh == m2);
            unsigned m3 = __reduce_max_sync(0xFFFFFFFFu, q2 ? bl : 0u);
            bool win = q2 && (bl == m3);
            int j = __reduce_min_sync(0xFFFFFFFFu, win ? bslot : 0x7FFFFFFF);
            if (lane == 0) kept[j] = 1;
            float4 bj = cbox[j];
            float aj = carea[j];
            if (c0 >= 0 && s0f > NEGF) {
                if (c0 == j) s0f = NEGF;
                else {
                    float ix1 = fmaxf(bj.x, b0.x), iy1 = fmaxf(bj.y, b0.y);
                    float ix2 = fminf(bj.z, b0.z), iy2 = fminf(bj.w, b0.w);
                    float inter = fmaxf(ix2 - ix1 + 1.f, 0.f) *
                                  fmaxf(iy2 - iy1 + 1.f, 0.f);
                    if (inter > 0.f) {   // exp(0)=1 exactly -> skip is exact
                        float iou = __fdividef(inter, aj + a0 - inter + 1e-16f);
                        s0f *= __expf(-2.f * iou * iou);
                    }
                }
            }
            if (c1 >= 0 && s1f > NEGF) {
                if (c1 == j) s1f = NEGF;
                else {
                    float ix1 = fmaxf(bj.x, b1.x), iy1 = fmaxf(bj.y, b1.y);
                    float ix2 = fminf(bj.z, b1.z), iy2 = fminf(bj.w, b1.w);
                    float inter = fmaxf(ix2 - ix1 + 1.f, 0.f) *
                                  fmaxf(iy2 - iy1 + 1.f, 0.f);
                    if (inter > 0.f) {
                        float iou = __fdividef(inter, aj + a1 - inter + 1e-16f);
                        s1f *= __expf(-2.f * iou * iou);
                    }
                }
            }
        }
    }
    __syncthreads();

    // ---- output: kept entries ranked by ORIGINAL key (desc), top-8 ----
    if (tid < 256) {
        unsigned bal = __ballot_sync(0xFFFFFFFFu, kept[tid] != 0);
        if (lane == 0) kmask[tid >> 5] = bal;
    }
    __syncthreads();
    if (tid < 256 && kept[tid]) {
        unsigned myh = __float_as_uint(cval[tid]);
        unsigned myl = cn[tid];
        int rank = 0;
        for (int u = 0; u < 256; u++) {
            if (kept[u]) {
                unsigned uh = __float_as_uint(cval[u]);
                if (uh > myh || (uh == myh && cn[u] > myl)) rank++;
            }
        }
        if (rank < 8) {
            float* o = out + (size_t)b * 48 + rank * 6;
            float4 bb = cbox[tid];
            o[0] = bb.x; o[1] = bb.y; o[2] = bb.z; o[3] = bb.w;
            o[4] = cval[tid];
            o[5] = (float)ccls[tid];
        }
    }
    if (tid >= 256 && tid < 264) {
        int K = 0;
#pragma unroll
        for (int ww = 0; ww < 8; ww++) K += __popc(kmask[ww]);
        int slot = tid - 256;
        if (slot >= K) {
            float* o = out + (size_t)b * 48 + slot * 6;
#pragma unroll
            for (int q2 = 0; q2 < 6; q2++) o[q2] = 0.f;
        }
    }
}

extern "C" void kernel_launch(void* const* d_in, const int* in_sizes, int n_in,
                              void* d_out, int out_size) {
    const float* p0 = (const float*)d_in[0];
    const float* p1 = (const float*)d_in[1];
    const float* p2 = (const float*)d_in[2];
    float* out = (float*)d_out;

    dim3 gridA(CPB, NB);
    score_kernel<<<gridA, BLKA>>>(p0, p1, p2);
    select_nms_kernel<<<NB, 1024>>>(p0, p1, p2, out);
}

// round 10
// speedup vs baseline: 1.6478x; 1.3713x over previous
#include <cuda_runtime.h>

#define NTOT  22743
#define NB    64
#define CAP   8192
#define NEGF  -1e9f

#define BLKA  256
#define RPT   8
#define CHUNK (BLKA * RPT)     // 2048
#define CPB   12               // 12*2048 >= 22743

typedef unsigned long long ull;

// per-image compacted candidate keys: (score_bits << 32) | ~anchor_idx
__device__ ull g_cand[(size_t)NB * CAP];
__device__ int g_cnt[NB];             // zeroed at init; kernel B resets after use

// anchors in pixels: level*3 + a  (w, h)
__constant__ float c_aw[9] = {116.f, 156.f, 373.f,  30.f, 62.f, 59.f,  10.f, 16.f, 33.f};
__constant__ float c_ah[9] = { 90.f, 198.f, 326.f,  61.f, 45.f, 119.f, 13.f, 30.f, 23.f};

__device__ __forceinline__ const float* rec_ptrf(const float* p0, const float* p1,
                                                 const float* p2, int b, int n) {
    if (n < 1083)  return p0 + ((size_t)b * 1083 + n) * 26;
    if (n < 5415)  return p1 + ((size_t)b * 4332 + (n - 1083)) * 26;
    return p2 + ((size_t)b * 17328 + (n - 5415)) * 26;
}

__device__ __forceinline__ int bucket_of(unsigned sb) {
    return min(max((int)(sb >> 15) - 0x7C00, 0), 1023);
}

// ---------------------------------------------------------------------------
// Kernel A (champion config): 2-D grid (chunk, image) so b is block-uniform.
// Phase 1: batched gate loads (MLP=8) -> smem queue. Phase 2: dense
// per-thread softmax. Gate on raw logits (no transcendentals).
// ---------------------------------------------------------------------------
__global__ __launch_bounds__(BLKA) void score_kernel(
    const float* __restrict__ p0, const float* __restrict__ p1,
    const float* __restrict__ p2) {

    __shared__ int q[CHUNK];
    __shared__ int qn;

    int tid = threadIdx.x;
    int lane = tid & 31;
    int b = blockIdx.y;
    int n0 = blockIdx.x * CHUNK;

    if (tid == 0) qn = 0;
    __syncthreads();

    // ---- phase 1: 8 independent gate loads per thread ----
    float2 gate[RPT];
    int nn[RPT];
#pragma unroll
    for (int r = 0; r < RPT; r++) {
        int n = n0 + r * BLKA + tid;
        nn[r] = n;
        if (n < NTOT)
            gate[r] = __ldg((const float2*)(rec_ptrf(p0, p1, p2, b, n) + 4));
        else
            gate[r] = make_float2(NEGF, NEGF);
    }

    // obj >= 0.6 <=> logit >= ln(1.5); loc >= 0.5 <=> logit >= 0
#pragma unroll
    for (int r = 0; r < RPT; r++) {
        bool pass = (nn[r] < NTOT) &&
                    (gate[r].x >= 0.40546510810816444f) && (gate[r].y >= 0.0f);
        unsigned m = __ballot_sync(0xFFFFFFFFu, pass);
        if (pass) {
            int leader = __ffs(m) - 1;
            int rank = __popc(m & ((1u << lane) - 1u));
            int bp = 0;
            if (lane == leader) bp = atomicAdd(&qn, __popc(m));
            bp = __shfl_sync(m, bp, leader);
            q[bp + rank] = nn[r];
        }
    }
    __syncthreads();

    int ne = qn;

    // ---- phase 2: dense per-thread softmax over queued records ----
    for (int i0 = 0; i0 < ne; i0 += BLKA) {
        int i = i0 + tid;
        bool act = i < ne;
        int n = act ? q[i] : 0;
        float sc = NEGF;
        if (act) {
            const float2* rec2 = (const float2*)rec_ptrf(p0, p1, p2, b, n);
            float2 g = __ldg(rec2 + 2);
            float2 l[10];
#pragma unroll
            for (int k = 0; k < 10; k++) l[k] = __ldg(rec2 + 3 + k);  // f6..f25
            float mx = fmaxf(l[0].x, l[0].y);
#pragma unroll
            for (int k = 1; k < 10; k++) mx = fmaxf(mx, fmaxf(l[k].x, l[k].y));
            float ssum = 0.f;
#pragma unroll
            for (int k = 0; k < 10; k++)
                ssum += __expf(l[k].x - mx) + __expf(l[k].y - mx);
            float obj = __fdividef(1.f, 1.f + __expf(-g.x));
            float conf = __fdividef(obj, ssum);             // obj * max(softmax)
            if (conf >= 0.05f) {
                float loc = __fdividef(1.f, 1.f + __expf(-g.y));
                sc = sqrtf(conf) * sqrtf(loc);
            }
        }
        bool push = act && (sc > 0.f);
        unsigned m = __ballot_sync(0xFFFFFFFFu, push);
        if (push) {
            int leader = __ffs(m) - 1;
            int rank = __popc(m & ((1u << lane) - 1u));
            int bp = 0;
            if (lane == leader) bp = atomicAdd(&g_cnt[b], __popc(m));
            bp = __shfl_sync(m, bp, leader);
            int p = bp + rank;
            if (p < CAP)
                g_cand[(size_t)b * CAP + p] =
                    ((ull)__float_as_uint(sc) << 32) | (unsigned)(~(unsigned)n);
        }
    }
}

// ---------------------------------------------------------------------------
// Kernel B: one block per image. Register-cached keys -> histogram +
// warp-shuffle suffix scan -> radix threshold -> compact -> low-barrier
// bitonic sort -> vectorized decode -> per-class parallel soft-NMS (one warp
// per class, exp skipped when boxes disjoint) -> parallel top-8 output.
// ---------------------------------------------------------------------------
__global__ __launch_bounds__(1024) void select_nms_kernel(
    const float* __restrict__ p0, const float* __restrict__ p1,
    const float* __restrict__ p2, float* __restrict__ out) {

    __shared__ ull    keys2[2048];
    __shared__ int    hist[1024];
    __shared__ int    suf[1024];
    __shared__ int    wsum[32];
    __shared__ int    wsuf[32];
    __shared__ float4 cbox[256];
    __shared__ float  cval[256];
    __shared__ float  carea[256];
    __shared__ int    ccls[256];
    __shared__ unsigned char kept[256];
    __shared__ unsigned char clist[20][64];
    __shared__ unsigned kmask[8];
    __shared__ int s_T, s_col, s_cnt;

    int tid = threadIdx.x;
    int lane = tid & 31;
    int w = tid >> 5;
    int b = blockIdx.x;

    if (tid == 0) {
        s_cnt = min(g_cnt[b], CAP);
        g_cnt[b] = 0;                        // reset for next call (graph-safe)
        s_col = 0;
        s_T = 0;
    }
    hist[tid] = 0;
    if (tid < 256) kept[tid] = 0;
    __syncthreads();

    int cnt = s_cnt;
    const ull* cand = g_cand + (size_t)b * CAP;

    // ---- register-cache keys (covers cnt <= 4096; tail handled directly) ----
    ull kr[4];
#pragma unroll
    for (int ii = 0; ii < 4; ii++) {
        int i = tid + ii * 1024;
        kr[ii] = (i < cnt) ? __ldg(cand + i) : 0ULL;
    }

    // ---- histogram of score bits ----
#pragma unroll
    for (int ii = 0; ii < 4; ii++) {
        int i = tid + ii * 1024;
        if (i < cnt) atomicAdd(&hist[bucket_of((unsigned)(kr[ii] >> 32))], 1);
    }
    for (int i = 4096 + tid; i < cnt; i += 1024)
        atomicAdd(&hist[bucket_of((unsigned)(__ldg(cand + i) >> 32))], 1);
    __syncthreads();

    // ---- suffix scan via warp shuffles ----
    int v = hist[tid];
#pragma unroll
    for (int s = 1; s < 32; s <<= 1) {
        int t2 = __shfl_down_sync(0xFFFFFFFFu, v, s);
        if (lane + s < 32) v += t2;
    }
    if (lane == 0) wsum[w] = v;
    __syncthreads();
    if (w == 0) {
        int x = wsum[lane];
        int tot0 = x;
#pragma unroll
        for (int s = 1; s < 32; s <<= 1) {
            int t2 = __shfl_down_sync(0xFFFFFFFFu, x, s);
            if (lane + s < 32) x += t2;
        }
        wsuf[lane] = x - tot0;               // exclusive suffix of later warps
    }
    __syncthreads();
    int sufv = v + wsuf[w];
    suf[tid] = sufv;
    __syncthreads();
    // threshold bucket T: largest i with suffix[i] >= 256 (0 if total < 256)
    if (sufv >= 256 && (tid == 1023 || suf[tid + 1] < 256)) s_T = tid;
    __syncthreads();
    int T = s_T;

    // ---- compact entries in buckets >= T ----
#pragma unroll
    for (int ii = 0; ii < 4; ii++) {
        int i = tid + ii * 1024;
        if (i < cnt && bucket_of((unsigned)(kr[ii] >> 32)) >= T) {
            int p = atomicAdd(&s_col, 1);
            if (p < 2048) keys2[p] = kr[ii];
        }
    }
    for (int i = 4096 + tid; i < cnt; i += 1024) {
        ull k = __ldg(cand + i);
        if (bucket_of((unsigned)(k >> 32)) >= T) {
            int p = atomicAdd(&s_col, 1);
            if (p < 2048) keys2[p] = k;
        }
    }
    __syncthreads();
    int col = min(s_col, 2048);
    int n2 = 256;
    while (n2 < col) n2 <<= 1;
    for (int i = col + tid; i < n2; i += 1024) keys2[i] = 0ULL;
    __syncthreads();

    // ---- bitonic sort (descending); j<32 passes are warp-local ----
    for (int k = 2; k <= n2; k <<= 1) {
        for (int j = k >> 1; j > 0; j >>= 1) {
            for (int i = tid; i < n2; i += 1024) {
                int l = i ^ j;
                if (l > i) {
                    ull a = keys2[i], c2 = keys2[l];
                    bool desc = ((i & k) == 0);
                    if ((a < c2) == desc) { keys2[i] = c2; keys2[l] = a; }
                }
            }
            if (j >= 32) __syncthreads(); else __syncwarp();
        }
    }
    __syncthreads();

    // ---- decode top-256 candidates (vectorized loads) ----
    if (tid < 256) {
        ull kk = keys2[tid];
        float4 bx = make_float4(0.f, 0.f, 0.f, 0.f);
        int cls = 255;               // never matches a class warp (0..19)
        float val = NEGF;
        float area = 0.f;
        if (kk != 0ULL) {
            unsigned n = ~(unsigned)(kk & 0xFFFFFFFFull);
            val = __uint_as_float((unsigned)(kk >> 32));
            int lvl, r, GG, G; float strd; const float* base;
            if (n < 1083u) {
                lvl = 0; r = (int)n;        GG = 361;  G = 19; strd = 32.f;
                base = p0 + (size_t)b * 1083 * 26;
            } else if (n < 5415u) {
                lvl = 1; r = (int)n - 1083; GG = 1444; G = 38; strd = 16.f;
                base = p1 + (size_t)b * 4332 * 26;
            } else {
                lvl = 2; r = (int)n - 5415; GG = 5776; G = 76; strd = 8.f;
                base = p2 + (size_t)b * 17328 * 26;
            }
            int a = r / GG; int cell = r - a * GG;
            int gy = cell / G; int gx = cell - gy * G;
            const float* rec = base + (size_t)r * 26;
            float tx, ty, tw, th, cl[20];
            if (((size_t)rec & 15) == 0) {
                float4 q0 = __ldg((const float4*)rec);            // f0..3
                float4 q1 = __ldg((const float4*)(rec + 4));      // f4..7
                float4 q2 = __ldg((const float4*)(rec + 8));
                float4 q3 = __ldg((const float4*)(rec + 12));
                float4 q4 = __ldg((const float4*)(rec + 16));
                float4 q5 = __ldg((const float4*)(rec + 20));     // f20..23
                float2 q6 = __ldg((const float2*)(rec + 24));
                tx = q0.x; ty = q0.y; tw = q0.z; th = q0.w;
                cl[0] = q1.z;  cl[1] = q1.w;
                cl[2] = q2.x;  cl[3] = q2.y;  cl[4] = q2.z;  cl[5] = q2.w;
                cl[6] = q3.x;  cl[7] = q3.y;  cl[8] = q3.z;  cl[9] = q3.w;
                cl[10] = q4.x; cl[11] = q4.y; cl[12] = q4.z; cl[13] = q4.w;
                cl[14] = q5.x; cl[15] = q5.y; cl[16] = q5.z; cl[17] = q5.w;
                cl[18] = q6.x; cl[19] = q6.y;
            } else {
                float2 q0 = __ldg((const float2*)rec);            // f0,f1
                float4 q1 = __ldg((const float4*)(rec + 2));      // f2..5
                float4 q2 = __ldg((const float4*)(rec + 6));      // f6..9
                float4 q3 = __ldg((const float4*)(rec + 10));
                float4 q4 = __ldg((const float4*)(rec + 14));
                float4 q5 = __ldg((const float4*)(rec + 18));     // f18..21
                float4 q6 = __ldg((const float4*)(rec + 22));     // f22..25
                tx = q0.x; ty = q0.y; tw = q1.x; th = q1.y;
                cl[0] = q2.x;  cl[1] = q2.y;  cl[2] = q2.z;  cl[3] = q2.w;
                cl[4] = q3.x;  cl[5] = q3.y;  cl[6] = q3.z;  cl[7] = q3.w;
                cl[8] = q4.x;  cl[9] = q4.y;  cl[10] = q4.z; cl[11] = q4.w;
                cl[12] = q5.x; cl[13] = q5.y; cl[14] = q5.z; cl[15] = q5.w;
                cl[16] = q6.x; cl[17] = q6.y; cl[18] = q6.z; cl[19] = q6.w;
            }
            float m = cl[0]; int ci = 0;
#pragma unroll
            for (int c = 1; c < 20; c++)
                if (cl[c] > m) { m = cl[c]; ci = c; }
            float sx = __fdividef(1.f, 1.f + __expf(-tx));
            float sy = __fdividef(1.f, 1.f + __expf(-ty));
            float cx = (sx + (float)gx) * strd;
            float cy = (sy + (float)gy) * strd;
            float ww2 = __expf(tw) * c_aw[lvl * 3 + a];
            float hh = __expf(th) * c_ah[lvl * 3 + a];
            float x1 = fminf(fmaxf(cx - 0.5f * ww2, 0.f), 608.f);
            float y1 = fminf(fmaxf(cy - 0.5f * hh, 0.f), 608.f);
            float x2 = fminf(fmaxf(cx + 0.5f * ww2, 0.f), 608.f);
            float y2 = fminf(fmaxf(cy + 0.5f * hh, 0.f), 608.f);
            bx = make_float4(x1, y1, x2, y2);
            area = (x2 - x1 + 1.f) * (y2 - y1 + 1.f);
            cls = ci;
        }
        cbox[tid] = bx;
        cval[tid] = val;
        carea[tid] = area;
        ccls[tid] = cls;
    }
    __syncthreads();

    // ---- per-class soft-NMS: warp w handles class w (classes decouple) ----
    if (w < 20) {
        int c = w;
        int cntc = 0;
        for (int g = 0; g < 8; g++) {
            int ci2 = g * 32 + lane;
            bool take = (ccls[ci2] == c);
            unsigned mm = __ballot_sync(0xFFFFFFFFu, take);
            if (take) {
                int pos = cntc + __popc(mm & ((1u << lane) - 1u));
                if (pos < 64) clist[c][pos] = (unsigned char)ci2;
            }
            cntc += __popc(mm);
        }
        if (cntc > 64) cntc = 64;
        __syncwarp();

        int cand0 = (lane < cntc) ? (int)clist[c][lane] : -1;
        int cand1 = (lane + 32 < cntc) ? (int)clist[c][lane + 32] : -1;
        float s0f = (cand0 >= 0) ? cval[cand0] : NEGF;
        float s1f = (cand1 >= 0) ? cval[cand1] : NEGF;
        float4 b0 = (cand0 >= 0) ? cbox[cand0] : make_float4(0.f, 0.f, 0.f, 0.f);
        float4 b1 = (cand1 >= 0) ? cbox[cand1] : make_float4(0.f, 0.f, 0.f, 0.f);
        float a0 = (cand0 >= 0) ? carea[cand0] : 0.f;
        float a1 = (cand1 >= 0) ? carea[cand1] : 0.f;

        while (true) {
            float sm; int im;
            if (s1f > s0f) { sm = s1f; im = cand1; }
            else           { sm = s0f; im = cand0; }   // tie -> lower cand idx
            unsigned kb = (sm > 0.f) ? __float_as_uint(sm) : 0u;
            unsigned gmax = __reduce_max_sync(0xFFFFFFFFu, kb);
            if (gmax < 0x3DCCCCCDu) break;             // 0.1f as bits
            int mi = (kb == gmax) ? im : 0x7FFFFFFF;
            int j = __reduce_min_sync(0xFFFFFFFFu, mi);
            if (lane == 0) kept[j] = 1;
            float4 bj = cbox[j];
            float aj = carea[j];
            if (cand0 >= 0) {
                if (cand0 == j) s0f = NEGF;
                else {
                    float ix1 = fmaxf(bj.x, b0.x), iy1 = fmaxf(bj.y, b0.y);
                    float ix2 = fminf(bj.z, b0.z), iy2 = fminf(bj.w, b0.w);
                    float inter = fmaxf(ix2 - ix1 + 1.f, 0.f) *
                                  fmaxf(iy2 - iy1 + 1.f, 0.f);
                    if (inter > 0.f) {   // exp(0)=1 exactly -> skip is exact
                        float iou = __fdividef(inter, aj + a0 - inter + 1e-16f);
                        s0f *= __expf(-2.f * iou * iou);
                    }
                }
            }
            if (cand1 >= 0) {
                if (cand1 == j) s1f = NEGF;
                else {
                    float ix1 = fmaxf(bj.x, b1.x), iy1 = fmaxf(bj.y, b1.y);
                    float ix2 = fminf(bj.z, b1.z), iy2 = fminf(bj.w, b1.w);
                    float inter = fmaxf(ix2 - ix1 + 1.f, 0.f) *
                                  fmaxf(iy2 - iy1 + 1.f, 0.f);
                    if (inter > 0.f) {
                        float iou = __fdividef(inter, aj + a1 - inter + 1e-16f);
                        s1f *= __expf(-2.f * iou * iou);
                    }
                }
            }
        }
    }
    __syncthreads();

    // ---- parallel output: rank kept candidates, write first 8 ----
    if (tid < 256) {
        unsigned bal = __ballot_sync(0xFFFFFFFFu, kept[tid] != 0);
        if (lane == 0) kmask[tid >> 5] = bal;
    }
    __syncthreads();
    if (tid < 256 && kept[tid]) {
        int pre = 0;
#pragma unroll
        for (int ww = 0; ww < 8; ww++)
            if (ww < (tid >> 5)) pre += __popc(kmask[ww]);
        pre += __popc(kmask[tid >> 5] & ((1u << lane) - 1u));
        if (pre < 8) {
            float* o = out + (size_t)b * 48 + pre * 6;
            float4 bb = cbox[tid];
            o[0] = bb.x; o[1] = bb.y; o[2] = bb.z; o[3] = bb.w;
            o[4] = cval[tid];
            o[5] = (float)ccls[tid];
        }
    }
    if (tid >= 256 && tid < 264) {
        int K = 0;
#pragma unroll
        for (int ww = 0; ww < 8; ww++) K += __popc(kmask[ww]);
        int slot = tid - 256;
        if (slot >= K) {
            float* o = out + (size_t)b * 48 + slot * 6;
#pragma unroll
            for (int q2 = 0; q2 < 6; q2++) o[q2] = 0.f;
        }
    }
}

extern "C" void kernel_launch(void* const* d_in, const int* in_sizes, int n_in,
                              void* d_out, int out_size) {
    const float* p0 = (const float*)d_in[0];
    const float* p1 = (const float*)d_in[1];
    const float* p2 = (const float*)d_in[2];
    float* out = (float*)d_out;

    dim3 gridA(CPB, NB);
    score_kernel<<<gridA, BLKA>>>(p0, p1, p2);
    select_nms_kernel<<<NB, 1024>>>(p0, p1, p2, out);
}